// round 3
// baseline (speedup 1.0000x reference)
#include <cuda_runtime.h>
#include <cuda_bf16.h>
#include <math.h>
#include <stdint.h>

// ---------------- problem constants ----------------
#define BATCH   32
#define SEQ     1000
#define DMODEL  256
#define PATCHSZ 160
#define NLAYERS 6
#define G3      768   // 3*DMODEL

// ---------------- scratch (device globals; no allocs allowed) ----------------
__device__ float g_x [BATCH * SEQ * DMODEL];   // residual stream x
__device__ float g_ln[BATCH * SEQ * DMODEL];   // layernorm(x) per layer
__device__ float g_xp[BATCH * SEQ * G3];       // input projection per layer
__device__ float g_emb[BATCH * DMODEL];        // pooled embedding

__device__ __forceinline__ float gelu_exact(float v) {
    return 0.5f * v * (1.0f + erff(v * 0.70710678118654752440f));
}
__device__ __forceinline__ float sigmoidf_(float v) {
    return 1.0f / (1.0f + expf(-v));
}

// =====================================================================
// Kernel 1: patchify conv (k=stride=160) + exact GELU + pos emb -> g_x
// grid 500, block 256.  Each CTA: 64 rows. conv_w column cached in regs.
// =====================================================================
__global__ __launch_bounds__(256) void k_conv(const float* __restrict__ wave,
                                              const float* __restrict__ cw,
                                              const float* __restrict__ pos) {
    __shared__ __align__(16) float sw[64 * PATCHSZ];   // 40 KB
    const int tid = threadIdx.x;
    const long base = (long)blockIdx.x * 64 * PATCHSZ;

    // cooperative copy of 64 contiguous patch rows (10240 floats)
    const float4* src = (const float4*)(wave + base);
    float4* dst = (float4*)sw;
#pragma unroll
    for (int i = 0; i < 10; i++) dst[tid + i * 256] = src[tid + i * 256];

    // weight column d = tid in registers (160 floats)
    float creg[PATCHSZ];
#pragma unroll
    for (int p = 0; p < PATCHSZ; p++) creg[p] = cw[p * DMODEL + tid];
    __syncthreads();

    const int row0 = blockIdx.x * 64;
    for (int r = 0; r < 64; r++) {
        const float4* wv = (const float4*)(sw + r * PATCHSZ);
        float acc = 0.0f;
#pragma unroll
        for (int i = 0; i < PATCHSZ / 4; i++) {
            float4 v = wv[i];
            acc += v.x * creg[4 * i + 0];
            acc += v.y * creg[4 * i + 1];
            acc += v.z * creg[4 * i + 2];
            acc += v.w * creg[4 * i + 3];
        }
        const int row = row0 + r;
        const int s = row % SEQ;
        g_x[(long)row * DMODEL + tid] = gelu_exact(acc) + pos[s * DMODEL + tid];
    }
}

// =====================================================================
// Kernel 2: layernorm over last dim (256). one warp per row.
// grid 4000, block 256 (8 rows / CTA). reads g_x, writes g_ln.
// =====================================================================
__global__ __launch_bounds__(256) void k_ln(const float* __restrict__ sc,
                                            const float* __restrict__ bi) {
    const int wid = threadIdx.x >> 5, lane = threadIdx.x & 31;
    const long row = (long)blockIdx.x * 8 + wid;
    const float4* xr = (const float4*)(g_x + row * DMODEL);
    float4 v0 = xr[lane];
    float4 v1 = xr[lane + 32];
    float s1 = v0.x + v0.y + v0.z + v0.w + v1.x + v1.y + v1.z + v1.w;
    float s2 = v0.x * v0.x + v0.y * v0.y + v0.z * v0.z + v0.w * v0.w
             + v1.x * v1.x + v1.y * v1.y + v1.z * v1.z + v1.w * v1.w;
#pragma unroll
    for (int o = 16; o > 0; o >>= 1) {
        s1 += __shfl_xor_sync(0xffffffffu, s1, o);
        s2 += __shfl_xor_sync(0xffffffffu, s2, o);
    }
    const float mu  = s1 * (1.0f / 256.0f);
    const float var = s2 * (1.0f / 256.0f) - mu * mu;
    const float inv = rsqrtf(var + 1e-5f);

    const int d0 = lane * 4, d1 = 128 + lane * 4;
    float4 sa = *(const float4*)(sc + d0), sb = *(const float4*)(sc + d1);
    float4 ba = *(const float4*)(bi + d0), bb = *(const float4*)(bi + d1);
    float4 o0, o1;
    o0.x = (v0.x - mu) * inv * sa.x + ba.x;  o0.y = (v0.y - mu) * inv * sa.y + ba.y;
    o0.z = (v0.z - mu) * inv * sa.z + ba.z;  o0.w = (v0.w - mu) * inv * sa.w + ba.w;
    o1.x = (v1.x - mu) * inv * sb.x + bb.x;  o1.y = (v1.y - mu) * inv * sb.y + bb.y;
    o1.z = (v1.z - mu) * inv * sb.z + bb.z;  o1.w = (v1.w - mu) * inv * sb.w + bb.w;
    float4* outr = (float4*)(g_ln + row * DMODEL);
    outr[lane] = o0;
    outr[lane + 32] = o1;
}

// =====================================================================
// Kernel 3: xp = g_ln[32000,256] @ W_ih^T[256,768] + b_ih -> g_xp
// tiled 128x128, K-chunk 32, 256 threads, 8x8 microtile.
// grid (250, 6).
// =====================================================================
__global__ __launch_bounds__(256) void k_gemm_xp(const float* __restrict__ W,
                                                 const float* __restrict__ bias) {
    __shared__ __align__(16) float As[128][36];   // [row][k] padded
    __shared__ __align__(16) float Bs[32][132];   // [k][col] padded (transposed)
    const int tid = threadIdx.x;
    const int tx = tid & 15, ty = tid >> 4;
    const int row0 = blockIdx.x * 128, col0 = blockIdx.y * 128;

    float acc[8][8];
#pragma unroll
    for (int i = 0; i < 8; i++)
#pragma unroll
        for (int j = 0; j < 8; j++) acc[i][j] = 0.0f;

    for (int k0 = 0; k0 < DMODEL; k0 += 32) {
#pragma unroll
        for (int it = 0; it < 4; it++) {          // A tile: 1024 float4
            int m = tid + it * 256;
            int r = m >> 3, kq = (m & 7) * 4;
            float4 v = *(const float4*)(g_ln + (long)(row0 + r) * DMODEL + k0 + kq);
            *(float4*)&As[r][kq] = v;
        }
#pragma unroll
        for (int it = 0; it < 4; it++) {          // B tile (transposed store)
            int m = tid + it * 256;
            int cc = m >> 3, kq = (m & 7) * 4;
            float4 v = *(const float4*)(W + (long)(col0 + cc) * DMODEL + k0 + kq);
            Bs[kq + 0][cc] = v.x; Bs[kq + 1][cc] = v.y;
            Bs[kq + 2][cc] = v.z; Bs[kq + 3][cc] = v.w;
        }
        __syncthreads();
#pragma unroll
        for (int kk = 0; kk < 32; kk++) {
            float a[8], b[8];
#pragma unroll
            for (int i = 0; i < 8; i++) a[i] = As[ty * 8 + i][kk];
            float4 b0 = *(float4*)&Bs[kk][tx * 8];
            float4 b1 = *(float4*)&Bs[kk][tx * 8 + 4];
            b[0] = b0.x; b[1] = b0.y; b[2] = b0.z; b[3] = b0.w;
            b[4] = b1.x; b[5] = b1.y; b[6] = b1.z; b[7] = b1.w;
#pragma unroll
            for (int i = 0; i < 8; i++)
#pragma unroll
                for (int j = 0; j < 8; j++) acc[i][j] += a[i] * b[j];
        }
        __syncthreads();
    }
    // epilogue: + bias, vectorized stores
#pragma unroll
    for (int i = 0; i < 8; i++) {
        const long row = row0 + ty * 8 + i;
        const int col = col0 + tx * 8;
        float4 o0, o1;
        o0.x = acc[i][0] + bias[col + 0]; o0.y = acc[i][1] + bias[col + 1];
        o0.z = acc[i][2] + bias[col + 2]; o0.w = acc[i][3] + bias[col + 3];
        o1.x = acc[i][4] + bias[col + 4]; o1.y = acc[i][5] + bias[col + 5];
        o1.z = acc[i][6] + bias[col + 6]; o1.w = acc[i][7] + bias[col + 7];
        *(float4*)(g_xp + row * G3 + col)     = o0;
        *(float4*)(g_xp + row * G3 + col + 4) = o1;
    }
}

// =====================================================================
// Kernel 4: GRU recurrence. cluster(4) per batch element.
// grid (4, 32), block 384. Weights register-resident (128 f32/thread).
// h replicated per-CTA in SMEM, double-buffered; chunk broadcast via
// st.shared::cluster; one barrier.cluster per step (release/acquire).
// Updates g_x in place: x += h_t.
// =====================================================================
__global__ void __cluster_dims__(4, 1, 1) __launch_bounds__(384, 1)
k_gru(const float* __restrict__ whh, const float* __restrict__ bhh) {
    __shared__ __align__(16) float h_buf[2][DMODEL];
    __shared__ float s_sums[192];

    const int c   = blockIdx.x;          // cluster rank 0..3 (cluster dims (4,1,1))
    const int b   = blockIdx.y;
    const int tid = threadIdx.x;
    const int w   = tid >> 5, l = tid & 31;
    const int o   = w * 16 + (l & 15);   // 0..191: CTA-local output index
    const int kh  = l >> 4;              // k half: 0 -> k[0,128), 1 -> k[128,256)
    const int gg  = o >> 6, dd = o & 63;
    const int R   = gg * DMODEL + c * 64 + dd;   // global gate row in [0,768)

    // weight slice into registers: 32 float4 = 128 floats
    float4 w4[32];
    const float4* wp = (const float4*)(whh + (long)R * DMODEL + kh * 128);
#pragma unroll
    for (int i = 0; i < 32; i++) w4[i] = wp[i];
    const float breg = (kh == 0) ? bhh[R] : 0.0f;

    // init both h buffers to 0
    for (int i = tid; i < 2 * DMODEL; i += 384) ((float*)h_buf)[i] = 0.0f;

    const float* xpb = g_xp + (long)b * SEQ * G3;
    float* xb = g_x + (long)b * SEQ * DMODEL;
    const int d = c * 64 + tid;          // gate threads: tid < 64

    // prefetch xp(t=0) and x(t=0) into registers
    float pxr = 0.f, pxz = 0.f, pxn = 0.f, pxv = 0.f;
    if (tid < 64) {
        pxr = xpb[d]; pxz = xpb[256 + d]; pxn = xpb[512 + d];
        pxv = xb[c * 64 + tid];
    }
    asm volatile("barrier.cluster.arrive.aligned;\n\tbarrier.cluster.wait.aligned;" ::: "memory");

    for (int t = 0; t < SEQ; t++) {
        const int p = t & 1;
        // ---- matvec: this thread's 128-long partial dot against h ----
        float acc = breg;
        const float4* hv = (const float4*)&h_buf[p][kh * 128];
#pragma unroll
        for (int i = 0; i < 32; i++) {
            float4 h4 = hv[i];
            float4 ww = w4[i];
            acc += ww.x * h4.x; acc += ww.y * h4.y;
            acc += ww.z * h4.z; acc += ww.w * h4.w;
        }
        acc += __shfl_xor_sync(0xffffffffu, acc, 16);   // combine k halves
        if (kh == 0) s_sums[o] = acc;
        __syncthreads();

        // ---- gates + h update + residual write (64 threads) ----
        if (tid < 64) {
            const float hr = s_sums[tid];
            const float hz = s_sums[64 + tid];
            const float hn = s_sums[128 + tid];
            const float rr = sigmoidf_(pxr + hr);
            const float zz = sigmoidf_(pxz + hz);
            const float nn = tanhf(pxn + rr * hn);
            const float hold = h_buf[p][c * 64 + tid];
            const float hnew = (1.0f - zz) * nn + zz * hold;

            // broadcast h chunk to all 4 CTAs' next buffer
            uint32_t la = (uint32_t)__cvta_generic_to_shared(&h_buf[p ^ 1][c * 64 + tid]);
#pragma unroll
            for (int r = 0; r < 4; r++) {
                uint32_t ra;
                asm volatile("mapa.shared::cluster.u32 %0, %1, %2;"
                             : "=r"(ra) : "r"(la), "r"(r));
                asm volatile("st.shared::cluster.f32 [%0], %1;"
                             :: "r"(ra), "f"(hnew) : "memory");
            }
            // residual: x_{l+1} = x_l + h_t  (pxv prefetched -> pure store)
            xb[(long)t * DMODEL + c * 64 + tid] = pxv + hnew;

            // prefetch next step
            if (t + 1 < SEQ) {
                const float* xpt = xpb + (long)(t + 1) * G3;
                pxr = xpt[d]; pxz = xpt[256 + d]; pxn = xpt[512 + d];
                pxv = xb[(long)(t + 1) * DMODEL + c * 64 + tid];
            }
        }
        // cluster barrier: release remote h stores / acquire peers'
        asm volatile("barrier.cluster.arrive.aligned;\n\tbarrier.cluster.wait.aligned;" ::: "memory");
    }
}

// =====================================================================
// Kernel 5: final layernorm + mean over seq -> g_emb. grid 32, block 256.
// =====================================================================
__global__ __launch_bounds__(256) void k_final(const float* __restrict__ sc,
                                               const float* __restrict__ bi) {
    const int b = blockIdx.x, tid = threadIdx.x;
    __shared__ float red[16];
    const float* xb = g_x + (long)b * SEQ * DMODEL;
    const float sce = sc[tid], bie = bi[tid];
    float accd = 0.0f;
    for (int t = 0; t < SEQ; t++) {
        const float v = xb[(long)t * DMODEL + tid];
        float s1 = v, s2 = v * v;
#pragma unroll
        for (int o = 16; o > 0; o >>= 1) {
            s1 += __shfl_xor_sync(0xffffffffu, s1, o);
            s2 += __shfl_xor_sync(0xffffffffu, s2, o);
        }
        const int wid = tid >> 5;
        if ((tid & 31) == 0) { red[wid] = s1; red[8 + wid] = s2; }
        __syncthreads();
        float S1 = 0.f, S2 = 0.f;
#pragma unroll
        for (int i = 0; i < 8; i++) { S1 += red[i]; S2 += red[8 + i]; }
        __syncthreads();
        const float mu  = S1 * (1.0f / 256.0f);
        const float var = S2 * (1.0f / 256.0f) - mu * mu;
        accd += (v - mu) * rsqrtf(var + 1e-5f) * sce + bie;
    }
    g_emb[b * DMODEL + tid] = accd * (1.0f / (float)SEQ);
}

// =====================================================================
// Kernel 6: classification head. grid 32, block 128.
// =====================================================================
__global__ __launch_bounds__(128) void k_head(const float* __restrict__ w1,
                                              const float* __restrict__ b1,
                                              const float* __restrict__ w2,
                                              const float* __restrict__ b2,
                                              float* __restrict__ out) {
    const int b = blockIdx.x, tid = threadIdx.x;
    __shared__ float es[DMODEL];
    __shared__ float h1s[128];
    es[tid]       = g_emb[b * DMODEL + tid];
    es[tid + 128] = g_emb[b * DMODEL + tid + 128];
    __syncthreads();
    float a = b1[tid];
#pragma unroll 8
    for (int dmi = 0; dmi < DMODEL; dmi++) a += es[dmi] * w1[dmi * 128 + tid];
    h1s[tid] = gelu_exact(a);
    __syncthreads();
    if (tid < 8) {
        float o = b2[tid];
#pragma unroll 8
        for (int j = 0; j < 128; j++) o += h1s[j] * w2[j * 8 + tid];
        out[b * 8 + tid] = o;
    }
}

// =====================================================================
// launch
// =====================================================================
extern "C" void kernel_launch(void* const* d_in, const int* in_sizes, int n_in,
                              void* d_out, int out_size) {
    const float* waveform = (const float*)d_in[0];
    const float* conv_w   = (const float*)d_in[1];
    const float* pos_emb  = (const float*)d_in[2];
    const float* ln_scale = (const float*)d_in[3];
    const float* ln_bias  = (const float*)d_in[4];
    const float* w_ih     = (const float*)d_in[5];
    const float* w_hh     = (const float*)d_in[6];
    const float* b_ih     = (const float*)d_in[7];
    const float* b_hh     = (const float*)d_in[8];
    const float* fnorm_s  = (const float*)d_in[9];
    const float* fnorm_b  = (const float*)d_in[10];
    const float* head_w1  = (const float*)d_in[11];
    const float* head_b1  = (const float*)d_in[12];
    const float* head_w2  = (const float*)d_in[13];
    const float* head_b2  = (const float*)d_in[14];
    float* out = (float*)d_out;

    k_conv<<<500, 256>>>(waveform, conv_w, pos_emb);

    for (int lyr = 0; lyr < NLAYERS; lyr++) {
        k_ln<<<4000, 256>>>(ln_scale + lyr * DMODEL, ln_bias + lyr * DMODEL);
        dim3 gg(250, 6);
        k_gemm_xp<<<gg, 256>>>(w_ih + (long)lyr * G3 * DMODEL, b_ih + lyr * G3);
        dim3 gr(4, BATCH);
        k_gru<<<gr, 384>>>(w_hh + (long)lyr * G3 * DMODEL, b_hh + lyr * G3);
    }

    k_final<<<BATCH, 256>>>(fnorm_s, fnorm_b);
    k_head<<<BATCH, 128>>>(head_w1, head_b1, head_w2, head_b2, out);
}